// round 5
// baseline (speedup 1.0000x reference)
#include <cuda_runtime.h>

typedef unsigned long long u64;

#define D_F 16
#define HID 16

// One constant image holding all weights/biases, duplicated as (w,w) f32x2
// payloads. Warp-uniform LDCU -> UR operands for FFMA2 (rt 2 instead of 3).
#define OFF_W1 0       // [d][c][h]      768 u64
#define OFF_W2 768     // [d][g][h]     4096 u64
#define OFF_W3 4864    // [d][g][o]      768 u64
#define OFF_B1 5632    //                256 u64
#define OFF_B2 5888    //                256 u64
#define OFF_B3 6144    //                 48 u64
#define CP_TOT 6192    // 49536 B < 64 KB constant bank

__constant__ u64 cP[CP_TOT];
__device__   u64 g_stage[CP_TOT];

// ---- f32x2 packed helpers ----
__device__ __forceinline__ u64 ffma2(u64 a, u64 b, u64 c) {
    u64 r;
    asm("fma.rn.f32x2 %0, %1, %2, %3;" : "=l"(r) : "l"(a), "l"(b), "l"(c));
    return r;
}
__device__ __forceinline__ u64 pack2f(float lo, float hi) {
    u64 r;
    asm("mov.b64 %0, {%1, %2};" : "=l"(r)
        : "r"(__float_as_uint(lo)), "r"(__float_as_uint(hi)));
    return r;
}
__device__ __forceinline__ u64 relu2(u64 v) {
    unsigned lo, hi;
    asm("mov.b64 {%0, %1}, %2;" : "=r"(lo), "=r"(hi) : "l"(v));
    float flo = fmaxf(__uint_as_float(lo), 0.0f);
    float fhi = fmaxf(__uint_as_float(hi), 0.0f);
    return pack2f(flo, fhi);
}
__device__ __forceinline__ float lo_of(u64 v) {
    unsigned lo, hi;
    asm("mov.b64 {%0, %1}, %2;" : "=r"(lo), "=r"(hi) : "l"(v));
    return __uint_as_float(lo);
}

// Build the duplicated/transposed constant image in a staging buffer.
__global__ void prep_kernel(const float* __restrict__ W1, const float* __restrict__ b1,
                            const float* __restrict__ W2, const float* __restrict__ b2,
                            const float* __restrict__ W3, const float* __restrict__ b3)
{
    int i = blockIdx.x * blockDim.x + threadIdx.x;
    if (i >= CP_TOT) return;
    float v;
    if (i < OFF_W2) {                       // W1: [d][c][h] <- [d][h][c]
        int j = i - OFF_W1, d = j / 48, r = j % 48, c = r / HID, h = r % HID;
        v = W1[d * 48 + h * 3 + c];
    } else if (i < OFF_W3) {                // W2: identity [d][g][h]
        v = W2[i - OFF_W2];
    } else if (i < OFF_B1) {                // W3: [d][g][o] <- [d][o][g]
        int j = i - OFF_W3, d = j / 48, r = j % 48, g = r / 3, o = r % 3;
        v = W3[d * 48 + o * HID + g];
    } else if (i < OFF_B2) {
        v = b1[i - OFF_B1];
    } else if (i < OFF_B3) {
        v = b2[i - OFF_B2];
    } else {
        v = b3[i - OFF_B3];
    }
    unsigned u = __float_as_uint(v);
    g_stage[i] = ((u64)u << 32) | (u64)u;   // (w, w)
}

__global__ __launch_bounds__(128, 4)
void fields_kernel(const float* __restrict__ x, float* __restrict__ out, int N)
{
    const int q    = blockIdx.x * blockDim.x + threadIdx.x;
    const int base = q * 4;                 // 4 points/thread = 2 f32x2 pairs

    if (base + 3 < N) {
        u64 xA[3], xB[3];
        #pragma unroll
        for (int c = 0; c < 3; c++) {
            ulonglong2 v = *reinterpret_cast<const ulonglong2*>(x + (size_t)c * N + base);
            xA[c] = v.x; xB[c] = v.y;       // LDG.128
        }

        #pragma unroll 1
        for (int d = 0; d < D_F; d++) {
            const u64* w1  = cP + OFF_W1 + d * 48;    // [c][h]
            const u64* w2  = cP + OFF_W2 + d * 256;   // [g][h]
            const u64* w3  = cP + OFF_W3 + d * 48;    // [g][o]
            const u64* b1d = cP + OFF_B1 + d * HID;
            const u64* b2d = cP + OFF_B2 + d * HID;
            const u64* b3d = cP + OFF_B3 + d * 3;

            // ---- layer 1: h1 = relu(W1 @ x + b1) ----
            u64 h1A[HID], h1B[HID];
            #pragma unroll
            for (int h = 0; h < HID; h++) {
                u64 bb = b1d[h];                      // LDCU.64 (uniform)
                h1A[h] = bb; h1B[h] = bb;
            }
            #pragma unroll
            for (int c = 0; c < 3; c++) {
                u64 xa = xA[c], xb = xB[c];
                #pragma unroll
                for (int h = 0; h < HID; h++) {
                    u64 w = w1[c * HID + h];          // uniform const -> UR
                    h1A[h] = ffma2(w, xa, h1A[h]);
                    h1B[h] = ffma2(w, xb, h1B[h]);
                }
            }
            #pragma unroll
            for (int h = 0; h < HID; h++) { h1A[h] = relu2(h1A[h]); h1B[h] = relu2(h1B[h]); }

            // ---- layers 2+3 fused ----
            u64 oA[3], oB[3];
            #pragma unroll
            for (int o = 0; o < 3; o++) {
                u64 t = b3d[o];
                oA[o] = t; oB[o] = t;
            }

            #pragma unroll
            for (int g = 0; g < HID; g++) {
                u64 a = b2d[g];                       // LDCU.64
                u64 b = a;
                #pragma unroll
                for (int h = 0; h < HID; h++) {
                    u64 w = w2[g * HID + h];          // uniform const -> UR
                    a = ffma2(w, h1A[h], a);
                    b = ffma2(w, h1B[h], b);
                }
                a = relu2(a); b = relu2(b);

                #pragma unroll
                for (int o = 0; o < 3; o++) {
                    u64 w = w3[g * 3 + o];
                    oA[o] = ffma2(w, a, oA[o]);
                    oB[o] = ffma2(w, b, oB[o]);
                }
            }

            #pragma unroll
            for (int o = 0; o < 3; o++) {
                *reinterpret_cast<ulonglong2*>(out + (size_t)(d * 3 + o) * N + base) =
                    make_ulonglong2(oA[o], oB[o]);    // STG.128
            }
        }
    } else {
        // scalar tail (unused when N % 4 == 0)
        for (int p = base; p < N && p >= 0; p++) {
            float xs[3];
            #pragma unroll
            for (int c = 0; c < 3; c++) xs[c] = x[(size_t)c * N + p];
            for (int d = 0; d < D_F; d++) {
                float h1[HID];
                for (int h = 0; h < HID; h++) {
                    float s = lo_of(cP[OFF_B1 + d * HID + h]);
                    for (int c = 0; c < 3; c++)
                        s += lo_of(cP[OFF_W1 + d * 48 + c * HID + h]) * xs[c];
                    h1[h] = fmaxf(s, 0.0f);
                }
                float o0 = lo_of(cP[OFF_B3 + d * 3 + 0]);
                float o1 = lo_of(cP[OFF_B3 + d * 3 + 1]);
                float o2 = lo_of(cP[OFF_B3 + d * 3 + 2]);
                for (int g = 0; g < HID; g++) {
                    float s = lo_of(cP[OFF_B2 + d * HID + g]);
                    for (int h = 0; h < HID; h++)
                        s += lo_of(cP[OFF_W2 + d * 256 + g * HID + h]) * h1[h];
                    s = fmaxf(s, 0.0f);
                    o0 += lo_of(cP[OFF_W3 + d * 48 + g * 3 + 0]) * s;
                    o1 += lo_of(cP[OFF_W3 + d * 48 + g * 3 + 1]) * s;
                    o2 += lo_of(cP[OFF_W3 + d * 48 + g * 3 + 2]) * s;
                }
                out[(size_t)(d * 3 + 0) * N + p] = o0;
                out[(size_t)(d * 3 + 1) * N + p] = o1;
                out[(size_t)(d * 3 + 2) * N + p] = o2;
            }
        }
    }
}

extern "C" void kernel_launch(void* const* d_in, const int* in_sizes, int n_in,
                              void* d_out, int out_size)
{
    const float* x  = (const float*)d_in[0];
    const float* W1 = (const float*)d_in[1];
    const float* b1 = (const float*)d_in[2];
    const float* W2 = (const float*)d_in[3];
    const float* b2 = (const float*)d_in[4];
    const float* W3 = (const float*)d_in[5];
    const float* b3 = (const float*)d_in[6];
    float* out = (float*)d_out;

    const int N = in_sizes[0] / 3;          // x is [1,3,N]

    // 1) Build duplicated/transposed weight image in staging (device global).
    prep_kernel<<<(CP_TOT + 255) / 256, 256>>>(W1, b1, W2, b2, W3, b3);

    // 2) Copy staging -> constant bank (async D2D memcpy; graph-capturable).
    void* stage_ptr = nullptr;
    cudaGetSymbolAddress(&stage_ptr, g_stage);
    cudaMemcpyToSymbolAsync(cP, stage_ptr, CP_TOT * sizeof(u64), 0,
                            cudaMemcpyDeviceToDevice, 0);

    // 3) Main kernel: weights from constant memory only.
    const int nq   = (N + 3) / 4;
    const int grid = (nq + 127) / 128;
    fields_kernel<<<grid, 128>>>(x, out, N);
}

// round 6
// speedup vs baseline: 2.2380x; 2.2380x over previous
#include <cuda_runtime.h>
#include <cuda_bf16.h>
#include <cstdint>

#define D_F 16

// ---- global prepped weight image ----
// Per field d (2048 B at d*2048):
//   +0    : W1 region, 4 tiles of 8x8 bf16 (128 B each): [hi n0-7][hi n8-15][lo n0-7][lo n8-15]
//           tile row = n(out ch within group), col = k: k<3 -> W1[d][n][k], k==3 -> b1[d][n], else 0
//   +512  : W2 region, 8 tiles: hi{(n0,k0),(n0,k1),(n1,k0),(n1,k1)} then lo same
//           tile row = g within group, col = h within group: W2[d][g][h]
//   +1536 : W3 region, 4 tiles: [hi k0][hi k1][lo k0][lo k1]; row = o (0 if o>=3), col = h
// Then: b2 f32 [16][16] at 32768, b3 padded f32 [16][8] at 33792.
#define B2_OFF 32768
#define B3_OFF 33792
#define IMG_BYTES 34304

__device__ __align__(16) unsigned char g_img[IMG_BYTES];

// ============ prep kernel ============
__global__ void prep_kernel(const float* __restrict__ W1, const float* __restrict__ b1,
                            const float* __restrict__ W2, const float* __restrict__ b2,
                            const float* __restrict__ W3, const float* __restrict__ b3)
{
    int i = blockIdx.x * blockDim.x + threadIdx.x;
    unsigned short* wimg = (unsigned short*)g_img;
    if (i < 8192) {                       // weight slots (hi+lo pair each)
        int d = i >> 9;
        int w = i & 511;
        int fb = d * 1024;                // u16 base of field
        float v = 0.0f;
        int hi_idx, lo_idx;
        if (w < 128) {                    // W1
            int s = w, tile = s >> 6, rr = (s >> 3) & 7, cc = s & 7;
            int n = tile * 8 + rr;
            if (cc < 3)       v = W1[d * 48 + n * 3 + cc];
            else if (cc == 3) v = b1[d * 16 + n];
            hi_idx = fb + s;        lo_idx = fb + 128 + s;
        } else if (w < 384) {             // W2
            int s = w - 128, tt = s >> 6, rr = (s >> 3) & 7, cc = s & 7;
            int nt = tt >> 1, kt = tt & 1;
            v = W2[d * 256 + (nt * 8 + rr) * 16 + (kt * 8 + cc)];
            hi_idx = fb + 256 + s;  lo_idx = fb + 512 + s;
        } else {                          // W3
            int s = w - 384, kt = s >> 6, rr = (s >> 3) & 7, cc = s & 7;
            v = (rr < 3) ? W3[d * 48 + rr * 16 + (kt * 8 + cc)] : 0.0f;
            hi_idx = fb + 768 + s;  lo_idx = fb + 896 + s;
        }
        __nv_bfloat16 hv = __float2bfloat16(v);
        float res = v - __bfloat162float(hv);
        __nv_bfloat16 lv = __float2bfloat16(res);
        wimg[hi_idx] = reinterpret_cast<unsigned short&>(hv);
        wimg[lo_idx] = reinterpret_cast<unsigned short&>(lv);
    } else if (i < 8192 + 256) {
        int j = i - 8192;
        ((float*)(g_img + B2_OFF))[j] = b2[j];
    } else if (i < 8192 + 256 + 128) {
        int j = i - 8448;
        int d = j >> 3, o = j & 7;
        ((float*)(g_img + B3_OFF))[j] = (o < 3) ? b3[d * 3 + o] : 0.0f;
    }
}

// ============ mma helpers ============
__device__ __forceinline__ void ldsm4(unsigned& r0, unsigned& r1, unsigned& r2, unsigned& r3,
                                      unsigned a) {
    asm volatile("ldmatrix.sync.aligned.m8n8.x4.shared.b16 {%0,%1,%2,%3}, [%4];"
                 : "=r"(r0), "=r"(r1), "=r"(r2), "=r"(r3) : "r"(a));
}
__device__ __forceinline__ void mma_k8(float c[4], unsigned a0, unsigned a1, unsigned b0) {
    asm volatile("mma.sync.aligned.m16n8k8.row.col.f32.bf16.bf16.f32 "
                 "{%0,%1,%2,%3}, {%4,%5}, {%6}, {%0,%1,%2,%3};"
                 : "+f"(c[0]), "+f"(c[1]), "+f"(c[2]), "+f"(c[3])
                 : "r"(a0), "r"(a1), "r"(b0));
}
__device__ __forceinline__ void mma_k16(float c[4], const unsigned a[4], unsigned b0, unsigned b1) {
    asm volatile("mma.sync.aligned.m16n8k16.row.col.f32.bf16.bf16.f32 "
                 "{%0,%1,%2,%3}, {%4,%5,%6,%7}, {%8,%9}, {%0,%1,%2,%3};"
                 : "+f"(c[0]), "+f"(c[1]), "+f"(c[2]), "+f"(c[3])
                 : "r"(a[0]), "r"(a[1]), "r"(a[2]), "r"(a[3]), "r"(b0), "r"(b1));
}
// pack (v0,v1) -> bf16x2 hi + bf16x2 lo residual (low half = v0, high half = v1)
__device__ __forceinline__ void split2(float v0, float v1, unsigned& hi, unsigned& lo) {
    asm("cvt.rn.bf16x2.f32 %0, %1, %2;" : "=r"(hi) : "f"(v1), "f"(v0));
    float h0 = __uint_as_float(hi << 16);
    float h1 = __uint_as_float(hi & 0xFFFF0000u);
    float r0 = v0 - h0, r1 = v1 - h1;
    asm("cvt.rn.bf16x2.f32 %0, %1, %2;" : "=r"(lo) : "f"(r1), "f"(r0));
}
__device__ __forceinline__ void relu_split(float v0, float v1, unsigned& hi, unsigned& lo) {
    split2(fmaxf(v0, 0.0f), fmaxf(v1, 0.0f), hi, lo);
}

// ============ main kernel ============
__global__ __launch_bounds__(256, 3)
void fields_mma_kernel(const float* __restrict__ x, float* __restrict__ out, int N)
{
    __shared__ __align__(16) unsigned char smem[IMG_BYTES];
    {
        const uint4* src = (const uint4*)g_img;
        uint4* dst = (uint4*)smem;
        for (int i = threadIdx.x; i < IMG_BYTES / 16; i += blockDim.x) dst[i] = src[i];
    }
    __syncthreads();

    const unsigned sbase = (unsigned)__cvta_generic_to_shared(smem);
    const float* sB2 = (const float*)(smem + B2_OFF);
    const float* sB3 = (const float*)(smem + B3_OFF);

    const int tid  = threadIdx.x;
    const int wid  = tid >> 5, lane = tid & 31;
    const int q    = lane & 3, r = lane >> 2;
    const unsigned lm_off = ((unsigned)(lane >> 3) << 7) + ((unsigned)(lane & 7) << 4);

    const int gwarp  = blockIdx.x * 8 + wid;
    const int nwarps = gridDim.x * 8;
    const int ntiles = (N + 15) >> 4;

    for (int tile = gwarp; tile < ntiles; tile += nwarps) {
        const int P = tile << 4;
        const int p0 = P + r, p1 = P + r + 8;
        const bool in0 = p0 < N, in1 = p1 < N;

        // ---- build x A-fragments (m16n8k8): k = {x0,x1,x2,1(bias),0,0,0,0} ----
        float v00 = 0.f, v01 = 0.f, v10 = 0.f, v11 = 0.f;
        if (q == 0) {
            if (in0) { v00 = x[p0]; v01 = x[N + p0]; }
            if (in1) { v10 = x[p1]; v11 = x[N + p1]; }
        } else if (q == 1) {
            if (in0) { v00 = x[2 * N + p0]; v01 = 1.0f; }
            if (in1) { v10 = x[2 * N + p1]; v11 = 1.0f; }
        }
        unsigned xa0h, xa0l, xa1h, xa1l;
        split2(v00, v01, xa0h, xa0l);
        split2(v10, v11, xa1h, xa1l);

        #pragma unroll 1
        for (int d = 0; d < D_F; d++) {
            const unsigned fbase = sbase + (unsigned)(d * 2048);

            // ---- layer 1 ----
            unsigned w1h0, w1h1, w1l0, w1l1;
            ldsm4(w1h0, w1h1, w1l0, w1l1, fbase + lm_off);
            float c0[4] = {0, 0, 0, 0}, c1[4] = {0, 0, 0, 0};
            mma_k8(c0, xa0h, xa1h, w1h0);  mma_k8(c1, xa0h, xa1h, w1h1);
            mma_k8(c0, xa0l, xa1l, w1h0);  mma_k8(c1, xa0l, xa1l, w1h1);
            mma_k8(c0, xa0h, xa1h, w1l0);  mma_k8(c1, xa0h, xa1h, w1l1);

            unsigned a2h[4], a2l[4];
            relu_split(c0[0], c0[1], a2h[0], a2l[0]);
            relu_split(c0[2], c0[3], a2h[1], a2l[1]);
            relu_split(c1[0], c1[1], a2h[2], a2l[2]);
            relu_split(c1[2], c1[3], a2h[3], a2l[3]);

            // ---- layer 2 ----
            unsigned w2h0, w2h1, w2h2, w2h3, w2l0, w2l1, w2l2, w2l3;
            ldsm4(w2h0, w2h1, w2h2, w2h3, fbase + 512 + lm_off);
            ldsm4(w2l0, w2l1, w2l2, w2l3, fbase + 1024 + lm_off);
            float2 bn0 = *(const float2*)&sB2[d * 16 + 2 * q];
            float2 bn1 = *(const float2*)&sB2[d * 16 + 8 + 2 * q];
            float e0[4] = {bn0.x, bn0.y, bn0.x, bn0.y};
            float e1[4] = {bn1.x, bn1.y, bn1.x, bn1.y};
            mma_k16(e0, a2h, w2h0, w2h1);  mma_k16(e1, a2h, w2h2, w2h3);
            mma_k16(e0, a2l, w2h0, w2h1);  mma_k16(e1, a2l, w2h2, w2h3);
            mma_k16(e0, a2h, w2l0, w2l1);  mma_k16(e1, a2h, w2l2, w2l3);

            unsigned a3h[4], a3l[4];
            relu_split(e0[0], e0[1], a3h[0], a3l[0]);
            relu_split(e0[2], e0[3], a3h[1], a3l[1]);
            relu_split(e1[0], e1[1], a3h[2], a3l[2]);
            relu_split(e1[2], e1[3], a3h[3], a3l[3]);

            // ---- layer 3 ----
            unsigned w3h0, w3h1, w3l0, w3l1;
            ldsm4(w3h0, w3h1, w3l0, w3l1, fbase + 1536 + lm_off);
            float2 b3v = *(const float2*)&sB3[d * 8 + 2 * q];
            float f0[4] = {b3v.x, b3v.y, b3v.x, b3v.y};
            mma_k16(f0, a3h, w3h0, w3h1);
            mma_k16(f0, a3l, w3h0, w3h1);
            mma_k16(f0, a3h, w3l0, w3l1);

            // ---- store: C cols = output channel o, rows = points ----
            const int o0 = 2 * q, o1 = 2 * q + 1;
            if (o0 < 3) {
                if (in0) out[(size_t)(d * 3 + o0) * N + p0] = f0[0];
                if (in1) out[(size_t)(d * 3 + o0) * N + p1] = f0[2];
            }
            if (o1 < 3) {
                if (in0) out[(size_t)(d * 3 + o1) * N + p0] = f0[1];
                if (in1) out[(size_t)(d * 3 + o1) * N + p1] = f0[3];
            }
        }
    }
}

extern "C" void kernel_launch(void* const* d_in, const int* in_sizes, int n_in,
                              void* d_out, int out_size)
{
    const float* x  = (const float*)d_in[0];
    const float* W1 = (const float*)d_in[1];
    const float* b1 = (const float*)d_in[2];
    const float* W2 = (const float*)d_in[3];
    const float* b2 = (const float*)d_in[4];
    const float* W3 = (const float*)d_in[5];
    const float* b3 = (const float*)d_in[6];
    float* out = (float*)d_out;

    const int N = in_sizes[0] / 3;   // x is [1,3,N]

    prep_kernel<<<(8576 + 255) / 256, 256>>>(W1, b1, W2, b2, W3, b3);

    // persistent grid: 3 CTAs/SM on 152 SMs (grid-stride tolerates any SM count)
    fields_mma_kernel<<<456, 256>>>(x, out, N);
}

// round 7
// speedup vs baseline: 2.4084x; 1.0761x over previous
#include <cuda_runtime.h>
#include <cuda_bf16.h>
#include <cstdint>

#define D_F 16

// ---- global prepped weight image ----
// Per field d (2048 B at d*2048):
//   +0    : W1, 4 tiles 8x8 bf16: [hi n0-7][hi n8-15][lo n0-7][lo n8-15]
//           row=n, col=k: k<3 -> W1[d][n][k], k==3 -> b1[d][n], else 0
//   +512  : W2, 8 tiles: hi{(n0,k0),(n0,k1),(n1,k0),(n1,k1)} then lo same; W2[d][g][h]
//   +1536 : W3, 4 tiles: [hi k0][hi k1][lo k0][lo k1]; row=o (0 pad o>=3), col=h
// b2 f32 [16][16] at 32768, b3 padded f32 [16][8] at 33792.
#define B2_OFF 32768
#define B3_OFF 33792
#define IMG_BYTES 34304

__device__ __align__(16) unsigned char g_img[IMG_BYTES];

// ============ prep kernel ============
__global__ void prep_kernel(const float* __restrict__ W1, const float* __restrict__ b1,
                            const float* __restrict__ W2, const float* __restrict__ b2,
                            const float* __restrict__ W3, const float* __restrict__ b3)
{
    int i = blockIdx.x * blockDim.x + threadIdx.x;
    unsigned short* wimg = (unsigned short*)g_img;
    if (i < 8192) {
        int d = i >> 9;
        int w = i & 511;
        int fb = d * 1024;
        float v = 0.0f;
        int hi_idx, lo_idx;
        if (w < 128) {                    // W1
            int s = w, tile = s >> 6, rr = (s >> 3) & 7, cc = s & 7;
            int n = tile * 8 + rr;
            if (cc < 3)       v = W1[d * 48 + n * 3 + cc];
            else if (cc == 3) v = b1[d * 16 + n];
            hi_idx = fb + s;        lo_idx = fb + 128 + s;
        } else if (w < 384) {             // W2
            int s = w - 128, tt = s >> 6, rr = (s >> 3) & 7, cc = s & 7;
            int nt = tt >> 1, kt = tt & 1;
            v = W2[d * 256 + (nt * 8 + rr) * 16 + (kt * 8 + cc)];
            hi_idx = fb + 256 + s;  lo_idx = fb + 512 + s;
        } else {                          // W3
            int s = w - 384, kt = s >> 6, rr = (s >> 3) & 7, cc = s & 7;
            v = (rr < 3) ? W3[d * 48 + rr * 16 + (kt * 8 + cc)] : 0.0f;
            hi_idx = fb + 768 + s;  lo_idx = fb + 896 + s;
        }
        __nv_bfloat16 hv = __float2bfloat16(v);
        float res = v - __bfloat162float(hv);
        __nv_bfloat16 lv = __float2bfloat16(res);
        wimg[hi_idx] = reinterpret_cast<unsigned short&>(hv);
        wimg[lo_idx] = reinterpret_cast<unsigned short&>(lv);
    } else if (i < 8192 + 256) {
        int j = i - 8192;
        ((float*)(g_img + B2_OFF))[j] = b2[j];
    } else if (i < 8192 + 256 + 128) {
        int j = i - 8448;
        int d = j >> 3, o = j & 7;
        ((float*)(g_img + B3_OFF))[j] = (o < 3) ? b3[d * 3 + o] : 0.0f;
    }
}

// ============ mma helpers ============
__device__ __forceinline__ void ldsm4(unsigned& r0, unsigned& r1, unsigned& r2, unsigned& r3,
                                      unsigned a) {
    asm volatile("ldmatrix.sync.aligned.m8n8.x4.shared.b16 {%0,%1,%2,%3}, [%4];"
                 : "=r"(r0), "=r"(r1), "=r"(r2), "=r"(r3) : "r"(a));
}
__device__ __forceinline__ void mma_k8(float c[4], unsigned a0, unsigned a1, unsigned b0) {
    asm volatile("mma.sync.aligned.m16n8k8.row.col.f32.bf16.bf16.f32 "
                 "{%0,%1,%2,%3}, {%4,%5}, {%6}, {%0,%1,%2,%3};"
                 : "+f"(c[0]), "+f"(c[1]), "+f"(c[2]), "+f"(c[3])
                 : "r"(a0), "r"(a1), "r"(b0));
}
__device__ __forceinline__ void mma_k16(float c[4], const unsigned a[4], unsigned b0, unsigned b1) {
    asm volatile("mma.sync.aligned.m16n8k16.row.col.f32.bf16.bf16.f32 "
                 "{%0,%1,%2,%3}, {%4,%5,%6,%7}, {%8,%9}, {%0,%1,%2,%3};"
                 : "+f"(c[0]), "+f"(c[1]), "+f"(c[2]), "+f"(c[3])
                 : "r"(a[0]), "r"(a[1]), "r"(a[2]), "r"(a[3]), "r"(b0), "r"(b1));
}
__device__ __forceinline__ void split2(float v0, float v1, unsigned& hi, unsigned& lo) {
    asm("cvt.rn.bf16x2.f32 %0, %1, %2;" : "=r"(hi) : "f"(v1), "f"(v0));
    float h0 = __uint_as_float(hi << 16);
    float h1 = __uint_as_float(hi & 0xFFFF0000u);
    float r0 = v0 - h0, r1 = v1 - h1;
    asm("cvt.rn.bf16x2.f32 %0, %1, %2;" : "=r"(lo) : "f"(r1), "f"(r0));
}
__device__ __forceinline__ void relu_split(float v0, float v1, unsigned& hi, unsigned& lo) {
    split2(fmaxf(v0, 0.0f), fmaxf(v1, 0.0f), hi, lo);
}

// ============ main kernel: 2 point-tiles (32 points) per warp iteration ============
__global__ __launch_bounds__(128, 6)
void fields_mma_kernel(const float* __restrict__ x, float* __restrict__ out, int N)
{
    __shared__ __align__(16) unsigned char smem[IMG_BYTES];
    {
        const uint4* src = (const uint4*)g_img;
        uint4* dst = (uint4*)smem;
        for (int i = threadIdx.x; i < IMG_BYTES / 16; i += blockDim.x) dst[i] = src[i];
    }
    __syncthreads();

    const unsigned sbase = (unsigned)__cvta_generic_to_shared(smem);
    const float* sB2 = (const float*)(smem + B2_OFF);
    const float* sB3 = (const float*)(smem + B3_OFF);

    const int tid  = threadIdx.x;
    const int wid  = tid >> 5, lane = tid & 31;
    const int q    = lane & 3, r = lane >> 2;
    const unsigned lm_off = ((unsigned)(lane >> 3) << 7) + ((unsigned)(lane & 7) << 4);

    const int gwarp  = blockIdx.x * 4 + wid;
    const int nwarps = gridDim.x * 4;
    const int ntiles = (N + 31) >> 5;            // 32 points per tile

    for (int tile = gwarp; tile < ntiles; tile += nwarps) {
        const int P = tile << 5;
        const int pA0 = P + r,      pA1 = P + r + 8;
        const int pB0 = P + r + 16, pB1 = P + r + 24;
        const bool iA0 = pA0 < N, iA1 = pA1 < N, iB0 = pB0 < N, iB1 = pB1 < N;

        // ---- x A-fragments for both tiles: k = {x0,x1,x2,1,0,0,0,0} ----
        float a00 = 0.f, a01 = 0.f, a10 = 0.f, a11 = 0.f;
        float b00 = 0.f, b01 = 0.f, b10 = 0.f, b11 = 0.f;
        if (q == 0) {
            if (iA0) { a00 = x[pA0]; a01 = x[N + pA0]; }
            if (iA1) { a10 = x[pA1]; a11 = x[N + pA1]; }
            if (iB0) { b00 = x[pB0]; b01 = x[N + pB0]; }
            if (iB1) { b10 = x[pB1]; b11 = x[N + pB1]; }
        } else if (q == 1) {
            if (iA0) { a00 = x[2 * N + pA0]; a01 = 1.0f; }
            if (iA1) { a10 = x[2 * N + pA1]; a11 = 1.0f; }
            if (iB0) { b00 = x[2 * N + pB0]; b01 = 1.0f; }
            if (iB1) { b10 = x[2 * N + pB1]; b11 = 1.0f; }
        }
        unsigned xAh0, xAl0, xAh1, xAl1, xBh0, xBl0, xBh1, xBl1;
        split2(a00, a01, xAh0, xAl0);  split2(a10, a11, xAh1, xAl1);
        split2(b00, b01, xBh0, xBl0);  split2(b10, b11, xBh1, xBl1);

        #pragma unroll 1
        for (int d = 0; d < D_F; d++) {
            const unsigned fbase = sbase + (unsigned)(d * 2048);

            // ================= layer 1 =================
            unsigned w1h0, w1h1, w1l0, w1l1;
            ldsm4(w1h0, w1h1, w1l0, w1l1, fbase + lm_off);
            float cA0[4] = {0, 0, 0, 0}, cA1[4] = {0, 0, 0, 0};
            float cB0[4] = {0, 0, 0, 0}, cB1[4] = {0, 0, 0, 0};
            mma_k8(cA0, xAh0, xAh1, w1h0);  mma_k8(cB0, xBh0, xBh1, w1h0);
            mma_k8(cA1, xAh0, xAh1, w1h1);  mma_k8(cB1, xBh0, xBh1, w1h1);
            mma_k8(cA0, xAl0, xAl1, w1h0);  mma_k8(cB0, xBl0, xBl1, w1h0);
            mma_k8(cA1, xAl0, xAl1, w1h1);  mma_k8(cB1, xBl0, xBl1, w1h1);
            mma_k8(cA0, xAh0, xAh1, w1l0);  mma_k8(cB0, xBh0, xBh1, w1l0);
            mma_k8(cA1, xAh0, xAh1, w1l1);  mma_k8(cB1, xBh0, xBh1, w1l1);

            unsigned aAh[4], aAl[4], aBh[4], aBl[4];
            relu_split(cA0[0], cA0[1], aAh[0], aAl[0]);
            relu_split(cA0[2], cA0[3], aAh[1], aAl[1]);
            relu_split(cA1[0], cA1[1], aAh[2], aAl[2]);
            relu_split(cA1[2], cA1[3], aAh[3], aAl[3]);
            relu_split(cB0[0], cB0[1], aBh[0], aBl[0]);
            relu_split(cB0[2], cB0[3], aBh[1], aBl[1]);
            relu_split(cB1[0], cB1[1], aBh[2], aBl[2]);
            relu_split(cB1[2], cB1[3], aBh[3], aBl[3]);

            // ================= layer 2 =================
            unsigned w2h0, w2h1, w2h2, w2h3, w2l0, w2l1, w2l2, w2l3;
            ldsm4(w2h0, w2h1, w2h2, w2h3, fbase + 512 + lm_off);
            ldsm4(w2l0, w2l1, w2l2, w2l3, fbase + 1024 + lm_off);
            float2 bn0 = *(const float2*)&sB2[d * 16 + 2 * q];
            float2 bn1 = *(const float2*)&sB2[d * 16 + 8 + 2 * q];
            float eA0[4] = {bn0.x, bn0.y, bn0.x, bn0.y};
            float eA1[4] = {bn1.x, bn1.y, bn1.x, bn1.y};
            float eB0[4] = {bn0.x, bn0.y, bn0.x, bn0.y};
            float eB1[4] = {bn1.x, bn1.y, bn1.x, bn1.y};
            mma_k16(eA0, aAh, w2h0, w2h1);  mma_k16(eB0, aBh, w2h0, w2h1);
            mma_k16(eA1, aAh, w2h2, w2h3);  mma_k16(eB1, aBh, w2h2, w2h3);
            mma_k16(eA0, aAl, w2h0, w2h1);  mma_k16(eB0, aBl, w2h0, w2h1);
            mma_k16(eA1, aAl, w2h2, w2h3);  mma_k16(eB1, aBl, w2h2, w2h3);
            mma_k16(eA0, aAh, w2l0, w2l1);  mma_k16(eB0, aBh, w2l0, w2l1);
            mma_k16(eA1, aAh, w2l2, w2l3);  mma_k16(eB1, aBh, w2l2, w2l3);

            relu_split(eA0[0], eA0[1], aAh[0], aAl[0]);
            relu_split(eA0[2], eA0[3], aAh[1], aAl[1]);
            relu_split(eA1[0], eA1[1], aAh[2], aAl[2]);
            relu_split(eA1[2], eA1[3], aAh[3], aAl[3]);
            relu_split(eB0[0], eB0[1], aBh[0], aBl[0]);
            relu_split(eB0[2], eB0[3], aBh[1], aBl[1]);
            relu_split(eB1[0], eB1[1], aBh[2], aBl[2]);
            relu_split(eB1[2], eB1[3], aBh[3], aBl[3]);

            // ================= layer 3 =================
            unsigned w3h0, w3h1, w3l0, w3l1;
            ldsm4(w3h0, w3h1, w3l0, w3l1, fbase + 1536 + lm_off);
            float2 b3v = *(const float2*)&sB3[d * 8 + 2 * q];
            float fA[4] = {b3v.x, b3v.y, b3v.x, b3v.y};
            float fB[4] = {b3v.x, b3v.y, b3v.x, b3v.y};
            mma_k16(fA, aAh, w3h0, w3h1);  mma_k16(fB, aBh, w3h0, w3h1);
            mma_k16(fA, aAl, w3h0, w3h1);  mma_k16(fB, aBl, w3h0, w3h1);
            mma_k16(fA, aAh, w3l0, w3l1);  mma_k16(fB, aBh, w3l0, w3l1);

            // ---- store ----
            const int o0 = 2 * q, o1 = 2 * q + 1;
            if (o0 < 3) {
                float* rowp = out + (size_t)(d * 3 + o0) * N;
                if (iA0) rowp[pA0] = fA[0];
                if (iA1) rowp[pA1] = fA[2];
                if (iB0) rowp[pB0] = fB[0];
                if (iB1) rowp[pB1] = fB[2];
            }
            if (o1 < 3) {
                float* rowp = out + (size_t)(d * 3 + o1) * N;
                if (iA0) rowp[pA0] = fA[1];
                if (iA1) rowp[pA1] = fA[3];
                if (iB0) rowp[pB0] = fB[1];
                if (iB1) rowp[pB1] = fB[3];
            }
        }
    }
}

extern "C" void kernel_launch(void* const* d_in, const int* in_sizes, int n_in,
                              void* d_out, int out_size)
{
    const float* x  = (const float*)d_in[0];
    const float* W1 = (const float*)d_in[1];
    const float* b1 = (const float*)d_in[2];
    const float* W2 = (const float*)d_in[3];
    const float* b2 = (const float*)d_in[4];
    const float* W3 = (const float*)d_in[5];
    const float* b3 = (const float*)d_in[6];
    float* out = (float*)d_out;

    const int N = in_sizes[0] / 3;   // x is [1,3,N]

    prep_kernel<<<(8576 + 255) / 256, 256>>>(W1, b1, W2, b2, W3, b3);

    // persistent grid: 6 CTAs/SM x 128 threads on 152 SMs (grid-stride safe)
    fields_mma_kernel<<<912, 128>>>(x, out, N);
}

// round 8
// speedup vs baseline: 3.5727x; 1.4834x over previous
#include <cuda_runtime.h>
#include <cuda_fp16.h>
#include <cstdint>

#define D_F 16

// ---- global prepped weight image (fp16 hi/lo) ----
// Per field d (2048 B at d*2048):
//   +0    : W1, 4 tiles 8x8 f16: [hi n0-7][hi n8-15][lo n0-7][lo n8-15]
//           row=n, col=k: k<3 -> W1[d][n][k], k==3 -> b1[d][n], else 0
//   +512  : W2, 8 tiles: hi{(n0,k0),(n0,k1),(n1,k0),(n1,k1)} then lo same; W2[d][g][h]
//   +1536 : W3, 4 tiles: [hi k0][hi k1][lo k0][lo k1]; row=o (0 pad o>=3), col=h
// b2 f32 [16][16] at 32768, b3 padded f32 [16][8] at 33792.
#define B2_OFF 32768
#define B3_OFF 33792
#define IMG_BYTES 34304

__device__ __align__(16) unsigned char g_img[IMG_BYTES];

// ============ prep kernel ============
__global__ void prep_kernel(const float* __restrict__ W1, const float* __restrict__ b1,
                            const float* __restrict__ W2, const float* __restrict__ b2,
                            const float* __restrict__ W3, const float* __restrict__ b3)
{
    int i = blockIdx.x * blockDim.x + threadIdx.x;
    unsigned short* wimg = (unsigned short*)g_img;
    if (i < 8192) {
        int d = i >> 9;
        int w = i & 511;
        int fb = d * 1024;
        float v = 0.0f;
        int hi_idx, lo_idx;
        if (w < 128) {                    // W1 (+ b1 in k=3 column)
            int s = w, tile = s >> 6, rr = (s >> 3) & 7, cc = s & 7;
            int n = tile * 8 + rr;
            if (cc < 3)       v = W1[d * 48 + n * 3 + cc];
            else if (cc == 3) v = b1[d * 16 + n];
            hi_idx = fb + s;        lo_idx = fb + 128 + s;
        } else if (w < 384) {             // W2
            int s = w - 128, tt = s >> 6, rr = (s >> 3) & 7, cc = s & 7;
            int nt = tt >> 1, kt = tt & 1;
            v = W2[d * 256 + (nt * 8 + rr) * 16 + (kt * 8 + cc)];
            hi_idx = fb + 256 + s;  lo_idx = fb + 512 + s;
        } else {                          // W3
            int s = w - 384, kt = s >> 6, rr = (s >> 3) & 7, cc = s & 7;
            v = (rr < 3) ? W3[d * 48 + rr * 16 + (kt * 8 + cc)] : 0.0f;
            hi_idx = fb + 768 + s;  lo_idx = fb + 896 + s;
        }
        __half hv = __float2half_rn(v);
        float res = v - __half2float(hv);
        __half lv = __float2half_rn(res);
        wimg[hi_idx] = reinterpret_cast<unsigned short&>(hv);
        wimg[lo_idx] = reinterpret_cast<unsigned short&>(lv);
    } else if (i < 8192 + 256) {
        int j = i - 8192;
        ((float*)(g_img + B2_OFF))[j] = b2[j];
    } else if (i < 8192 + 256 + 128) {
        int j = i - 8448;
        int d = j >> 3, o = j & 7;
        ((float*)(g_img + B3_OFF))[j] = (o < 3) ? b3[d * 3 + o] : 0.0f;
    }
}

// ============ mma / cvt helpers (fp16) ============
__device__ __forceinline__ void ldsm4(unsigned& r0, unsigned& r1, unsigned& r2, unsigned& r3,
                                      unsigned a) {
    asm volatile("ldmatrix.sync.aligned.m8n8.x4.shared.b16 {%0,%1,%2,%3}, [%4];"
                 : "=r"(r0), "=r"(r1), "=r"(r2), "=r"(r3) : "r"(a));
}
__device__ __forceinline__ void mma_k8(float c[4], unsigned a0, unsigned a1, unsigned b0) {
    asm volatile("mma.sync.aligned.m16n8k8.row.col.f32.f16.f16.f32 "
                 "{%0,%1,%2,%3}, {%4,%5}, {%6}, {%0,%1,%2,%3};"
                 : "+f"(c[0]), "+f"(c[1]), "+f"(c[2]), "+f"(c[3])
                 : "r"(a0), "r"(a1), "r"(b0));
}
__device__ __forceinline__ void mma_k16(float c[4], const unsigned a[4], unsigned b0, unsigned b1) {
    asm volatile("mma.sync.aligned.m16n8k16.row.col.f32.f16.f16.f32 "
                 "{%0,%1,%2,%3}, {%4,%5,%6,%7}, {%8,%9}, {%0,%1,%2,%3};"
                 : "+f"(c[0]), "+f"(c[1]), "+f"(c[2]), "+f"(c[3])
                 : "r"(a[0]), "r"(a[1]), "r"(a[2]), "r"(a[3]), "r"(b0), "r"(b1));
}
// pack (v0,v1) -> f16x2 (low half = v0)
__device__ __forceinline__ unsigned cvt2(float v0, float v1) {
    unsigned h;
    asm("cvt.rn.f16x2.f32 %0, %1, %2;" : "=r"(h) : "f"(v1), "f"(v0));
    return h;
}
// relu + pack in 2 ops
__device__ __forceinline__ unsigned cvt2_relu(float v0, float v1) {
    unsigned h = cvt2(v0, v1);
    unsigned r;
    asm("max.f16x2 %0, %1, %2;" : "=r"(r) : "r"(h), "r"(0u));
    return r;
}

// ============ main kernel: 2 point-tiles (32 points) per warp iteration ============
__global__ __launch_bounds__(128, 7)
void fields_mma_kernel(const float* __restrict__ x, float* __restrict__ out, int N)
{
    __shared__ __align__(16) unsigned char smem[IMG_BYTES];
    {
        const uint4* src = (const uint4*)g_img;
        uint4* dst = (uint4*)smem;
        for (int i = threadIdx.x; i < IMG_BYTES / 16; i += blockDim.x) dst[i] = src[i];
    }
    __syncthreads();

    const unsigned sbase = (unsigned)__cvta_generic_to_shared(smem);
    const float* sB2 = (const float*)(smem + B2_OFF);
    const float* sB3 = (const float*)(smem + B3_OFF);

    const int tid  = threadIdx.x;
    const int wid  = tid >> 5, lane = tid & 31;
    const int q    = lane & 3, r = lane >> 2;
    const unsigned lm_off = ((unsigned)(lane >> 3) << 7) + ((unsigned)(lane & 7) << 4);

    const int gwarp  = blockIdx.x * 4 + wid;
    const int nwarps = gridDim.x * 4;
    const int ntiles = (N + 31) >> 5;            // 32 points per tile

    for (int tile = gwarp; tile < ntiles; tile += nwarps) {
        const int P = tile << 5;
        const int pA0 = P + r,      pA1 = P + r + 8;
        const int pB0 = P + r + 16, pB1 = P + r + 24;
        const bool iA0 = pA0 < N, iA1 = pA1 < N, iB0 = pB0 < N, iB1 = pB1 < N;

        // ---- x A-fragments (single fp16): k = {x0,x1,x2,1,0,0,0,0} ----
        float a00 = 0.f, a01 = 0.f, a10 = 0.f, a11 = 0.f;
        float b00 = 0.f, b01 = 0.f, b10 = 0.f, b11 = 0.f;
        if (q == 0) {
            if (iA0) { a00 = x[pA0]; a01 = x[N + pA0]; }
            if (iA1) { a10 = x[pA1]; a11 = x[N + pA1]; }
            if (iB0) { b00 = x[pB0]; b01 = x[N + pB0]; }
            if (iB1) { b10 = x[pB1]; b11 = x[N + pB1]; }
        } else if (q == 1) {
            if (iA0) { a00 = x[2 * N + pA0]; a01 = 1.0f; }
            if (iA1) { a10 = x[2 * N + pA1]; a11 = 1.0f; }
            if (iB0) { b00 = x[2 * N + pB0]; b01 = 1.0f; }
            if (iB1) { b10 = x[2 * N + pB1]; b11 = 1.0f; }
        }
        const unsigned xA0 = cvt2(a00, a01), xA1 = cvt2(a10, a11);
        const unsigned xB0 = cvt2(b00, b01), xB1 = cvt2(b10, b11);

        #pragma unroll 1
        for (int d = 0; d < D_F; d++) {
            const unsigned fbase = sbase + (unsigned)(d * 2048);

            // ================= layer 1 (A single, W hi+lo) =================
            unsigned w1h0, w1h1, w1l0, w1l1;
            ldsm4(w1h0, w1h1, w1l0, w1l1, fbase + lm_off);
            float cA0[4] = {0, 0, 0, 0}, cA1[4] = {0, 0, 0, 0};
            float cB0[4] = {0, 0, 0, 0}, cB1[4] = {0, 0, 0, 0};
            mma_k8(cA0, xA0, xA1, w1h0);  mma_k8(cB0, xB0, xB1, w1h0);
            mma_k8(cA1, xA0, xA1, w1h1);  mma_k8(cB1, xB0, xB1, w1h1);
            mma_k8(cA0, xA0, xA1, w1l0);  mma_k8(cB0, xB0, xB1, w1l0);
            mma_k8(cA1, xA0, xA1, w1l1);  mma_k8(cB1, xB0, xB1, w1l1);

            unsigned aA[4], aB[4];
            aA[0] = cvt2_relu(cA0[0], cA0[1]);  aA[1] = cvt2_relu(cA0[2], cA0[3]);
            aA[2] = cvt2_relu(cA1[0], cA1[1]);  aA[3] = cvt2_relu(cA1[2], cA1[3]);
            aB[0] = cvt2_relu(cB0[0], cB0[1]);  aB[1] = cvt2_relu(cB0[2], cB0[3]);
            aB[2] = cvt2_relu(cB1[0], cB1[1]);  aB[3] = cvt2_relu(cB1[2], cB1[3]);

            // ================= layer 2 =================
            unsigned w2h0, w2h1, w2h2, w2h3, w2l0, w2l1, w2l2, w2l3;
            ldsm4(w2h0, w2h1, w2h2, w2h3, fbase + 512 + lm_off);
            ldsm4(w2l0, w2l1, w2l2, w2l3, fbase + 1024 + lm_off);
            float2 bn0 = *(const float2*)&sB2[d * 16 + 2 * q];
            float2 bn1 = *(const float2*)&sB2[d * 16 + 8 + 2 * q];
            float eA0[4] = {bn0.x, bn0.y, bn0.x, bn0.y};
            float eA1[4] = {bn1.x, bn1.y, bn1.x, bn1.y};
            float eB0[4] = {bn0.x, bn0.y, bn0.x, bn0.y};
            float eB1[4] = {bn1.x, bn1.y, bn1.x, bn1.y};
            mma_k16(eA0, aA, w2h0, w2h1);  mma_k16(eB0, aB, w2h0, w2h1);
            mma_k16(eA1, aA, w2h2, w2h3);  mma_k16(eB1, aB, w2h2, w2h3);
            mma_k16(eA0, aA, w2l0, w2l1);  mma_k16(eB0, aB, w2l0, w2l1);
            mma_k16(eA1, aA, w2l2, w2l3);  mma_k16(eB1, aB, w2l2, w2l3);

            unsigned gA[4], gB[4];
            gA[0] = cvt2_relu(eA0[0], eA0[1]);  gA[1] = cvt2_relu(eA0[2], eA0[3]);
            gA[2] = cvt2_relu(eA1[0], eA1[1]);  gA[3] = cvt2_relu(eA1[2], eA1[3]);
            gB[0] = cvt2_relu(eB0[0], eB0[1]);  gB[1] = cvt2_relu(eB0[2], eB0[3]);
            gB[2] = cvt2_relu(eB1[0], eB1[1]);  gB[3] = cvt2_relu(eB1[2], eB1[3]);

            // ================= layer 3 =================
            unsigned w3h0, w3h1, w3l0, w3l1;
            ldsm4(w3h0, w3h1, w3l0, w3l1, fbase + 1536 + lm_off);
            float2 b3v = *(const float2*)&sB3[d * 8 + 2 * q];
            float fA[4] = {b3v.x, b3v.y, b3v.x, b3v.y};
            float fB[4] = {b3v.x, b3v.y, b3v.x, b3v.y};
            mma_k16(fA, gA, w3h0, w3h1);  mma_k16(fB, gB, w3h0, w3h1);
            mma_k16(fA, gA, w3l0, w3l1);  mma_k16(fB, gB, w3l0, w3l1);

            // ---- store ----
            const int o0 = 2 * q, o1 = 2 * q + 1;
            if (o0 < 3) {
                float* rowp = out + (size_t)(d * 3 + o0) * N;
                if (iA0) rowp[pA0] = fA[0];
                if (iA1) rowp[pA1] = fA[2];
                if (iB0) rowp[pB0] = fB[0];
                if (iB1) rowp[pB1] = fB[2];
            }
            if (o1 < 3) {
                float* rowp = out + (size_t)(d * 3 + o1) * N;
                if (iA0) rowp[pA0] = fA[1];
                if (iA1) rowp[pA1] = fA[3];
                if (iB0) rowp[pB0] = fB[1];
                if (iB1) rowp[pB1] = fB[3];
            }
        }
    }
}

extern "C" void kernel_launch(void* const* d_in, const int* in_sizes, int n_in,
                              void* d_out, int out_size)
{
    const float* x  = (const float*)d_in[0];
    const float* W1 = (const float*)d_in[1];
    const float* b1 = (const float*)d_in[2];
    const float* W2 = (const float*)d_in[3];
    const float* b2 = (const float*)d_in[4];
    const float* W3 = (const float*)d_in[5];
    const float* b3 = (const float*)d_in[6];
    float* out = (float*)d_out;

    const int N = in_sizes[0] / 3;   // x is [1,3,N]

    prep_kernel<<<(8576 + 255) / 256, 256>>>(W1, b1, W2, b2, W3, b3);

    // persistent grid: 7 CTAs/SM x 128 threads on 152 SMs (grid-stride safe)
    fields_mma_kernel<<<1064, 128>>>(x, out, N);
}